// round 13
// baseline (speedup 1.0000x reference)
#include <cuda_runtime.h>
#include <cstdint>
#include <math.h>

#define K_DIM 1024
#define N_EXPERTS 64
#define BM 128
#define KCHUNK 16
#define NLOCAL 32                 // chunks per group (512 K each)
#define XS_STRIDE 132             // [k][token] floats
#define WS_STRIDE 68              // [k][expert] floats
#define XS_FLOATS (KCHUNK * XS_STRIDE)             // 2112
#define GRP_FLOATS (KCHUNK * (XS_STRIDE + WS_STRIDE))  // 3200
#define LG_STRIDE 68
#define SMEM_FLOATS 8704
#define FULL 0xffffffffu

typedef unsigned long long u64;

#define GBAR(id) asm volatile("bar.sync %0, 128;" :: "r"(id) : "memory")

// one instruction, two exact fp32 FMAs (lanewise)
static __device__ __forceinline__ void ffma2(u64& d, u64 a, u64 b) {
    asm("fma.rn.f32x2 %0, %1, %2, %0;" : "+l"(d) : "l"(a), "l"(b));
}
static __device__ __forceinline__ u64 bcast2(float v) {
    u64 r;
    asm("mov.b64 %0, {%1, %1};" : "=l"(r) : "f"(v));
    return r;
}
static __device__ __forceinline__ float lo32(u64 u) { return __uint_as_float((unsigned)u); }
static __device__ __forceinline__ float hi32(u64 u) { return __uint_as_float((unsigned)(u >> 32)); }

__global__ __launch_bounds__(256, 2)
void router_f32x2_kernel(const float* __restrict__ x,
                         const float* __restrict__ Wm,
                         const float* __restrict__ bias,
                         float* __restrict__ out,
                         int num_tokens) {
    extern __shared__ float smem[];
    const int tid  = threadIdx.x;
    const int gid  = tid >> 7;          // k-split group 0/1
    const int gtid = tid & 127;
    const int bm   = blockIdx.x * BM;
    const int kbase = gid * (K_DIM / 2);

    float* xs = smem + gid * GRP_FLOATS;         // [16][132]
    float* ws = xs + XS_FLOATS;                  // [16][68]

    // loader mapping: kq = k-granule 0..3, row = 0..31
    const int kq  = gtid & 3;
    const int row = gtid >> 2;

    // compute mapping: txk = expert oct 0..7, tym = token oct 0..15
    const int txk = gtid & 7;
    const int tym = gtid >> 3;

    auto load_chunk = [&](int c) {
        const int ko = kbase + c * KCHUNK + kq * 4;
        float4 xv[4], wv[2];
        const float* gx = x + (size_t)(bm + row) * K_DIM + ko;
        #pragma unroll
        for (int i = 0; i < 4; ++i)
            xv[i] = __ldg((const float4*)(gx + (size_t)(32 * i) * K_DIM));
        const float* gw = Wm + (size_t)row * K_DIM + ko;
        #pragma unroll
        for (int i = 0; i < 2; ++i)
            wv[i] = __ldg((const float4*)(gw + (size_t)(32 * i) * K_DIM));
        #pragma unroll
        for (int i = 0; i < 4; ++i) {
            xs[(kq * 4 + 0) * XS_STRIDE + row + 32 * i] = xv[i].x;
            xs[(kq * 4 + 1) * XS_STRIDE + row + 32 * i] = xv[i].y;
            xs[(kq * 4 + 2) * XS_STRIDE + row + 32 * i] = xv[i].z;
            xs[(kq * 4 + 3) * XS_STRIDE + row + 32 * i] = xv[i].w;
        }
        #pragma unroll
        for (int i = 0; i < 2; ++i) {
            ws[(kq * 4 + 0) * WS_STRIDE + row + 32 * i] = wv[i].x;
            ws[(kq * 4 + 1) * WS_STRIDE + row + 32 * i] = wv[i].y;
            ws[(kq * 4 + 2) * WS_STRIDE + row + 32 * i] = wv[i].z;
            ws[(kq * 4 + 3) * WS_STRIDE + row + 32 * i] = wv[i].w;
        }
    };

    // acc2[p][j]: token pair (tym*8+2p, tym*8+2p+1), expert txk*8+j
    u64 acc2[4][8];
    #pragma unroll
    for (int p = 0; p < 4; ++p)
        #pragma unroll
        for (int j = 0; j < 8; ++j) acc2[p][j] = 0ULL;

    const int barid = 1 + gid;

    load_chunk(0);
    GBAR(barid);

    #pragma unroll 1
    for (int c = 0; c < NLOCAL; ++c) {
        #pragma unroll 4
        for (int k = 0; k < KCHUNK; ++k) {
            // a: 4 packed token-pairs, directly from smem (16B aligned)
            const ulonglong2 ap0 = *(const ulonglong2*)&xs[k * XS_STRIDE + tym * 8];
            const ulonglong2 ap1 = *(const ulonglong2*)&xs[k * XS_STRIDE + tym * 8 + 4];
            const u64 ap[4] = {ap0.x, ap0.y, ap1.x, ap1.y};
            // b: 8 expert scalars, broadcast-packed
            const float4 b0 = *(const float4*)&ws[k * WS_STRIDE + txk * 8];
            const float4 b1 = *(const float4*)&ws[k * WS_STRIDE + txk * 8 + 4];
            const float bn[8] = {b0.x, b0.y, b0.z, b0.w, b1.x, b1.y, b1.z, b1.w};
            u64 bd[8];
            #pragma unroll
            for (int j = 0; j < 8; ++j) bd[j] = bcast2(bn[j]);
            #pragma unroll
            for (int p = 0; p < 4; ++p)
                #pragma unroll
                for (int j = 0; j < 8; ++j)
                    ffma2(acc2[p][j], ap[p], bd[j]);
        }
        GBAR(barid);
        if (c + 1 < NLOCAL) {
            load_chunk(c + 1);
            GBAR(barid);
        }
    }

    // ---- merge k-split partials (float-wise, order (p,j,s)) ----
    __syncthreads();
    if (gid == 1) {
        #pragma unroll
        for (int p = 0; p < 4; ++p)
            #pragma unroll
            for (int j = 0; j < 8; ++j) {
                smem[gtid * 65 + (p * 8 + j) * 2 + 0] = lo32(acc2[p][j]);
                smem[gtid * 65 + (p * 8 + j) * 2 + 1] = hi32(acc2[p][j]);
            }
    }
    __syncthreads();
    if (gid != 0) return;

    float arr[64];
    #pragma unroll
    for (int p = 0; p < 4; ++p)
        #pragma unroll
        for (int j = 0; j < 8; ++j) {
            arr[(p * 8 + j) * 2 + 0] = lo32(acc2[p][j]) + smem[gtid * 65 + (p * 8 + j) * 2 + 0];
            arr[(p * 8 + j) * 2 + 1] = hi32(acc2[p][j]) + smem[gtid * 65 + (p * 8 + j) * 2 + 1];
        }
    GBAR(1);

    // ---- dump summed logits [token][expert] ----
    #pragma unroll
    for (int p = 0; p < 4; ++p)
        #pragma unroll
        for (int s = 0; s < 2; ++s)
            #pragma unroll
            for (int j = 0; j < 8; ++j)
                smem[(tym * 8 + 2 * p + s) * LG_STRIDE + txk * 8 + j] = arr[(p * 8 + j) * 2 + s];
    GBAR(1);

    // ---- exact per-token epilogue: thread gtid owns token bm+gtid ----
    const float4* b4 = (const float4*)bias;
    const float4* lrow = (const float4*)&smem[gtid * LG_STRIDE];

    float v[64];
    #pragma unroll
    for (int q = 0; q < 16; ++q) {
        const float4 lv = lrow[q];
        const float4 bv = __ldg(b4 + q);
        v[q * 4 + 0] = lv.x + bv.x;
        v[q * 4 + 1] = lv.y + bv.y;
        v[q * 4 + 2] = lv.z + bv.z;
        v[q * 4 + 3] = lv.w + bv.w;
    }
    float m1 = -INFINITY, m2 = -INFINITY;
    int i1 = 0, i2 = 0;
    #pragma unroll
    for (int e = 0; e < 64; ++e) {
        if (v[e] > m1) { m2 = m1; i2 = i1; m1 = v[e]; i1 = e; }
        else if (v[e] > m2) { m2 = v[e]; i2 = e; }
    }
    float s = 0.0f;
    #pragma unroll
    for (int e = 0; e < 64; ++e) s += __expf(v[e] - m1);

    const float inv = 1.0f / s;
    const int tk = bm + gtid;
    float* oid = out + (size_t)num_tokens * 2;
    *(float2*)&out[tk * 2] = make_float2(inv, __expf(m2 - m1) * inv);
    *(float2*)&oid[tk * 2] = make_float2((float)i1, (float)i2);
}

extern "C" void kernel_launch(void* const* d_in, const int* in_sizes, int n_in,
                              void* d_out, int out_size) {
    const float* x = (const float*)d_in[0];   // [8,4096,1024]
    const float* W = (const float*)d_in[1];   // [64,1024]
    const float* b = (const float*)d_in[2];   // [64]
    float* out = (float*)d_out;

    const int num_tokens = in_sizes[0] / K_DIM;   // 32768
    const int grid = num_tokens / BM;             // 256

    cudaFuncSetAttribute(router_f32x2_kernel,
                         cudaFuncAttributeMaxDynamicSharedMemorySize, SMEM_FLOATS * 4);
    router_f32x2_kernel<<<grid, 256, SMEM_FLOATS * 4>>>(x, W, b, out, num_tokens);
}